// round 9
// baseline (speedup 1.0000x reference)
#include <cuda_runtime.h>
#include <cuda_bf16.h>
#include <cstdint>

// Blur_82471962018173: depthwise separable 4x4 FIR ([1,3,3,1]/4 per axis),
// input (4,128,513,513) f32, pad=1 both sides, output (4,128,512,512) f32.
//
// R9: 16-byte cp.async ring. DEPTH=6 (slot reuse distance 2 iterations with
// an intervening barrier — DEPTH=7 raced, R8 lesson), 12 blocks/SM, and
// compile-time row phase via template dispatch (W_IN == 1 mod 4 =>
// d(r) = (D0+r)&3) so the 7-tap window select folds away per unrolled body.

#define W_IN    513
#define W_OUT   512
#define ROWS    64
#define NT      128
#define DEPTH   6
#define SLOTS   8
#define SSTR    520                 // floats per slot (multiple of 4)
#define PLANE   (W_IN * W_IN)       // 263169
#define TOTALF  (512 * PLANE)       // total input floats (fits in int32)

__device__ __forceinline__ void cp16(uint32_t dst, const float* src, int sz) {
    asm volatile("cp.async.cg.shared.global [%0], [%1], 16, %2;"
                 :: "r"(dst), "l"(src), "r"(sz));
}

template<int D0>
__device__ __forceinline__ void run_strip(
    const float* __restrict__ in, float* __restrict__ op,
    float (*ring)[SSTR], uint32_t sring,
    int pbase, int y0, int t, int x4)
{
    auto issue_row = [&](int r) {
        const int yy = y0 - 1 + r;
        const bool rowok = ((unsigned)yy < (unsigned)W_IN);
        const int a  = pbase + yy * W_IN - 1;    // flat idx of x=-1
        const int gs = a & ~3;                   // aligned copy start
        const uint32_t sb = sring + (uint32_t)(r & (SLOTS - 1)) * (SSTR * 4);

        const int gk = gs + (t << 2);
        const bool ok = rowok && (gk >= 0) && (gk + 4 <= TOTALF);
        cp16(sb + (t << 4), in + gk, ok ? 16 : 0);
        if (t < 2) {                             // chunks 128,129
            const int gk2 = gs + ((128 + t) << 2);
            const bool ok2 = rowok && (gk2 >= 0) && (gk2 + 4 <= TOTALF);
            cp16(sb + ((128 + t) << 4), in + gk2, ok2 ? 16 : 0);
        }
    };

    #pragma unroll
    for (int j = 0; j < DEPTH; ++j) {
        issue_row(j);
        asm volatile("cp.async.commit_group;");
    }

    float4 hw[4];                                // rolling h-filtered rows

    #pragma unroll 4
    for (int r = 0; r < ROWS + 3; ++r) {
        if (r + DEPTH < ROWS + 3) issue_row(r + DEPTH);
        asm volatile("cp.async.commit_group;");          // empty on tail
        asm volatile("cp.async.wait_group %0;" :: "n"(DEPTH - 1));
        __syncthreads();

        const int d = (D0 + r) & 3;              // constant per unrolled body

        const float* sm = ring[r & (SLOTS - 1)];
        const float4 A = *(const float4*)(sm + x4);
        const float4 B = *(const float4*)(sm + x4 + 4);
        const float4 C = *(const float4*)(sm + x4 + 8);

        // window v0..v6 = in[x4-1 .. x4+5]  (smem j = x + 1 + d)
        float v0, v1, v2, v3, v4, v5, v6;
        if (d == 0)      { v0=A.x; v1=A.y; v2=A.z; v3=A.w; v4=B.x; v5=B.y; v6=B.z; }
        else if (d == 1) { v0=A.y; v1=A.z; v2=A.w; v3=B.x; v4=B.y; v5=B.z; v6=B.w; }
        else if (d == 2) { v0=A.z; v1=A.w; v2=B.x; v3=B.y; v4=B.z; v5=B.w; v6=C.x; }
        else             { v0=A.w; v1=B.x; v2=B.y; v3=B.z; v4=B.w; v5=C.x; v6=C.y; }
        if (t == 0)      v0 = 0.f;   // x=-1 horizontal pad
        if (t == NT - 1) v6 = 0.f;   // x=513 horizontal pad

        float4 hc;
        hc.x = 0.25f * (v0 + v3) + 0.75f * (v1 + v2);
        hc.y = 0.25f * (v1 + v4) + 0.75f * (v2 + v3);
        hc.z = 0.25f * (v2 + v5) + 0.75f * (v3 + v4);
        hc.w = 0.25f * (v3 + v6) + 0.75f * (v4 + v5);
        hw[r & 3] = hc;

        if (r >= 3) {
            const float4 a = hw[(r - 3) & 3];
            const float4 b = hw[(r - 2) & 3];
            const float4 c = hw[(r - 1) & 3];
            float4 o;
            o.x = 0.25f * (a.x + hc.x) + 0.75f * (b.x + c.x);
            o.y = 0.25f * (a.y + hc.y) + 0.75f * (b.y + c.y);
            o.z = 0.25f * (a.z + hc.z) + 0.75f * (b.z + c.z);
            o.w = 0.25f * (a.w + hc.w) + 0.75f * (b.w + c.w);
            *(float4*)(op + (size_t)(r - 3) * W_OUT) = o;
        }
    }
}

__global__ __launch_bounds__(NT, 12)
void blur_kernel(const float* __restrict__ in, float* __restrict__ out) {
    __shared__ __align__(16) float ring[SLOTS][SSTR];

    const int nc = blockIdx.z;
    const int y0 = blockIdx.y * ROWS;
    const int t  = threadIdx.x;
    const int x4 = t << 2;

    const int pbase = nc * PLANE;
    float* op = out + (size_t)nc * (W_OUT * W_OUT) + (size_t)y0 * W_OUT + x4;
    const uint32_t sring = (uint32_t)__cvta_generic_to_shared(&ring[0][0]);

    // phase of row r=0: ((pbase + (y0-1)*W_IN - 1) & 3); rows advance by 1 mod 4
    const int D0 = (pbase + (y0 - 1) * W_IN - 1) & 3;
    switch (D0) {
    case 0:  run_strip<0>(in, op, ring, sring, pbase, y0, t, x4); break;
    case 1:  run_strip<1>(in, op, ring, sring, pbase, y0, t, x4); break;
    case 2:  run_strip<2>(in, op, ring, sring, pbase, y0, t, x4); break;
    default: run_strip<3>(in, op, ring, sring, pbase, y0, t, x4); break;
    }
}

extern "C" void kernel_launch(void* const* d_in, const int* in_sizes, int n_in,
                              void* d_out, int out_size) {
    const float* in = (const float*)d_in[0];   // (4,128,513,513) f32
    float* out = (float*)d_out;                // (4,128,512,512) f32
    dim3 grid(1, W_OUT / ROWS, 4 * 128);       // 8 row-strips x 512 planes
    blur_kernel<<<grid, NT>>>(in, out);
}

// round 10
// speedup vs baseline: 1.0017x; 1.0017x over previous
#include <cuda_runtime.h>
#include <cuda_bf16.h>
#include <cstdint>

// Blur_82471962018173: depthwise separable 4x4 FIR ([1,3,3,1]/4 per axis),
// input (4,128,513,513) f32, pad=1 both sides, output (4,128,512,512) f32.
//
// R10: 16-byte cp.async ring with PAIRWISE row processing: one commit group,
// one wait_group(2), one __syncthreads per 2 rows (36 barriers/strip vs 67).
// Slot-reuse distance stays 2 iterations with an intervening barrier (the
// R8/R9 safety invariant). Compile-time row phase via template dispatch.

#define W_IN    513
#define W_OUT   512
#define ROWS    64
#define NT      128
#define SLOTS   8
#define SSTR    520                 // floats per slot (multiple of 4)
#define PLANE   (W_IN * W_IN)       // 263169
#define TOTALF  (512 * PLANE)       // total input floats (fits in int32)

__device__ __forceinline__ void cp16(uint32_t dst, const float* src, int sz) {
    asm volatile("cp.async.cg.shared.global [%0], [%1], 16, %2;"
                 :: "r"(dst), "l"(src), "r"(sz));
}

template<int D0>
__device__ __forceinline__ void run_strip(
    const float* __restrict__ in, float* __restrict__ op,
    float (*ring)[SSTR], uint32_t sring,
    int pbase, int y0, int t, int x4)
{
    auto issue_row = [&](int r) {
        const int yy = y0 - 1 + r;
        const bool rowok = ((unsigned)yy < (unsigned)W_IN);
        const int a  = pbase + yy * W_IN - 1;    // flat idx of x=-1
        const int gs = a & ~3;                   // aligned copy start
        const uint32_t sb = sring + (uint32_t)(r & (SLOTS - 1)) * (SSTR * 4);

        const int gk = gs + (t << 2);
        const bool ok = rowok && (gk >= 0) && (gk + 4 <= TOTALF);
        cp16(sb + (t << 4), in + gk, ok ? 16 : 0);
        if (t < 2) {                             // chunks 128,129
            const int gk2 = gs + ((128 + t) << 2);
            const bool ok2 = rowok && (gk2 >= 0) && (gk2 + 4 <= TOTALF);
            cp16(sb + ((128 + t) << 4), in + gk2, ok2 ? 16 : 0);
        }
    };

    float4 hw[4];                                // rolling h-filtered rows

    auto hfilt = [&](int r) {
        const int d = (D0 + r) & 3;              // compile-time per body
        const float* sm = ring[r & (SLOTS - 1)];
        const float4 A = *(const float4*)(sm + x4);
        const float4 B = *(const float4*)(sm + x4 + 4);
        const float4 C = *(const float4*)(sm + x4 + 8);
        // window v0..v6 = in[x4-1 .. x4+5]  (smem j = x + 1 + d)
        float v0, v1, v2, v3, v4, v5, v6;
        if (d == 0)      { v0=A.x; v1=A.y; v2=A.z; v3=A.w; v4=B.x; v5=B.y; v6=B.z; }
        else if (d == 1) { v0=A.y; v1=A.z; v2=A.w; v3=B.x; v4=B.y; v5=B.z; v6=B.w; }
        else if (d == 2) { v0=A.z; v1=A.w; v2=B.x; v3=B.y; v4=B.z; v5=B.w; v6=C.x; }
        else             { v0=A.w; v1=B.x; v2=B.y; v3=B.z; v4=B.w; v5=C.x; v6=C.y; }
        if (t == 0)      v0 = 0.f;   // x=-1 horizontal pad
        if (t == NT - 1) v6 = 0.f;   // x=513 horizontal pad
        float4 hc;
        hc.x = 0.25f * (v0 + v3) + 0.75f * (v1 + v2);
        hc.y = 0.25f * (v1 + v4) + 0.75f * (v2 + v3);
        hc.z = 0.25f * (v2 + v5) + 0.75f * (v3 + v4);
        hc.w = 0.25f * (v3 + v6) + 0.75f * (v4 + v5);
        hw[r & 3] = hc;
    };

    auto vout = [&](int r) {                     // output row r-3 from hw
        const float4 a = hw[(r - 3) & 3];
        const float4 b = hw[(r - 2) & 3];
        const float4 c = hw[(r - 1) & 3];
        const float4 hc = hw[r & 3];
        float4 o;
        o.x = 0.25f * (a.x + hc.x) + 0.75f * (b.x + c.x);
        o.y = 0.25f * (a.y + hc.y) + 0.75f * (b.y + c.y);
        o.z = 0.25f * (a.z + hc.z) + 0.75f * (b.z + c.z);
        o.w = 0.25f * (a.w + hc.w) + 0.75f * (b.w + c.w);
        *(float4*)(op + (size_t)(r - 3) * W_OUT) = o;
    };

    // pre-issue: groups {0,1,2}, {3,4}, {5,6}
    issue_row(0); issue_row(1); issue_row(2);
    asm volatile("cp.async.commit_group;");
    issue_row(3); issue_row(4);
    asm volatile("cp.async.commit_group;");
    issue_row(5); issue_row(6);
    asm volatile("cp.async.commit_group;");

    // prologue: rows 0..2 fill the vertical window
    asm volatile("cp.async.wait_group 2;");
    __syncthreads();
    hfilt(0); hfilt(1); hfilt(2);
    __syncthreads();   // protect slots 0..2 before loop's first issues

    #pragma unroll 2
    for (int k = 0; k < ROWS / 2; ++k) {
        const int r0 = 3 + 2 * k;                // rows r0, r0+1 this iter
        if (k < 30) {                            // rows r0+4, r0+5 (<= 66)
            issue_row(r0 + 4);
            issue_row(r0 + 5);
        }
        asm volatile("cp.async.commit_group;");  // empty on tail iters
        asm volatile("cp.async.wait_group 2;");  // rows <= r0+1 complete
        __syncthreads();

        hfilt(r0);     vout(r0);
        hfilt(r0 + 1); vout(r0 + 1);
    }
}

__global__ __launch_bounds__(NT, 12)
void blur_kernel(const float* __restrict__ in, float* __restrict__ out) {
    __shared__ __align__(16) float ring[SLOTS][SSTR];

    const int nc = blockIdx.z;
    const int y0 = blockIdx.y * ROWS;
    const int t  = threadIdx.x;
    const int x4 = t << 2;

    const int pbase = nc * PLANE;
    float* op = out + (size_t)nc * (W_OUT * W_OUT) + (size_t)y0 * W_OUT + x4;
    const uint32_t sring = (uint32_t)__cvta_generic_to_shared(&ring[0][0]);

    // phase of row r=0: ((pbase + (y0-1)*W_IN - 1) & 3); rows advance by 1 mod 4
    const int D0 = (pbase + (y0 - 1) * W_IN - 1) & 3;
    switch (D0) {
    case 0:  run_strip<0>(in, op, ring, sring, pbase, y0, t, x4); break;
    case 1:  run_strip<1>(in, op, ring, sring, pbase, y0, t, x4); break;
    case 2:  run_strip<2>(in, op, ring, sring, pbase, y0, t, x4); break;
    default: run_strip<3>(in, op, ring, sring, pbase, y0, t, x4); break;
    }
}

extern "C" void kernel_launch(void* const* d_in, const int* in_sizes, int n_in,
                              void* d_out, int out_size) {
    const float* in = (const float*)d_in[0];   // (4,128,513,513) f32
    float* out = (float*)d_out;                // (4,128,512,512) f32
    dim3 grid(1, W_OUT / ROWS, 4 * 128);       // 8 row-strips x 512 planes
    blur_kernel<<<grid, NT>>>(in, out);
}